// round 14
// baseline (speedup 1.0000x reference)
#include <cuda_runtime.h>

#define SEQ   4096
#define CIN   7
#define NUMK  74
#define KH    8
#define KW    3
#define D     1536
#define TLEN  (SEQ * KW)   // 12288
#define NBLK  444          // one block per resident slot (148 SMs x 3): perfectly balanced
#define SPER  10           // max rows per block (blocks own 9 or 10 rows)
#define NH    (3 * SPER)   // 30 conv h-values per block
#define NT    384          // threads per block
#define WLEN  (3 * SPER + 7)  // 37 window values per channel
#define WPAD  40

// ---- packed f32x2 helpers (sm_100a) ----
typedef unsigned long long u64;
#define F2PACK(d, lo, hi)   asm("mov.b64 %0, {%1, %2};"      : "=l"(d) : "f"(lo), "f"(hi))
#define F2UNPACK(lo, hi, s) asm("mov.b64 {%0, %1}, %2;"      : "=f"(lo), "=f"(hi) : "l"(s))
#define F2MUL(d, a, b)      asm("mul.rn.f32x2 %0, %1, %2;"   : "=l"(d) : "l"(a), "l"(b))
#define F2ADD(d, a, b)      asm("add.rn.f32x2 %0, %1, %2;"   : "=l"(d) : "l"(a), "l"(b))
#define F2FMA(d, a, b, c)   asm("fma.rn.f32x2 %0, %1, %2, %3;" : "=l"(d) : "l"(a), "l"(b), "l"(c))

// dynamic smem layout (floats):
#define SM_CONV   0                              // [NH][512] = 15360
#define SM_WCS    (SM_CONV + NH * 512)           // [KH][76]  = 608
#define SM_SXA    (SM_WCS + KH * 76)             // [CIN][40] = 280
#define SM_SXB    (SM_SXA + CIN * WPAD)          // [CIN][40] = 280
#define SM_M      (SM_SXB + CIN * WPAD)          // [SPER][8] = 80  (NON-duplicated multiplicities)
#define SMEM_BYTES ((SM_M + SPER * 8) * 4)

// packed-pair conv for one column: h in [hr, hr+2*nsteps), results to convS[h][g]
// dual staggered window copies make every (v_j, v_{j+1}) pair one aligned LDS.64
__device__ __forceinline__ void conv_col(
    const float* __restrict__ sxa,    // copyA: v[i]
    const float* __restrict__ sxb,    // copyB: v[i+1] at index i
    const float* __restrict__ wcsS,   // [k][76]
    int o, int g, int hr, int nsteps, // hr even
    float* __restrict__ convS)
{
    u64 wp[8];
#pragma unroll
    for (int k = 0; k < 8; k++) {
        float w = wcsS[k * 76 + o];
        F2PACK(wp[k], w, w);
    }
    // ring: P[j] = (v[hr+j], v[hr+j+1]);  even j from copyA, odd j from copyB
    u64 P[8];
#pragma unroll
    for (int j = 0; j < 8; j++) {
        P[j] = (j & 1) ? *(const u64*)(sxb + hr + j - 1)
                       : *(const u64*)(sxa + hr + j);
    }

#pragma unroll
    for (int t = 0; t < nsteps; t++) {
        const int h = hr + 2 * t;
        u64 acc;
        F2MUL(acc, wp[0], P[(2 * t) & 7]);
#pragma unroll
        for (int k = 1; k < 8; k++)
            F2FMA(acc, wp[k], P[(2 * t + k) & 7], acc);
        float lo, hi;
        F2UNPACK(lo, hi, acc);
        convS[h * 512 + g]       = lo;
        convS[(h + 1) * 512 + g] = hi;
        if (t < nsteps - 1) {
            P[(2 * t) & 7]     = *(const u64*)(sxa + hr + 2 * t + 8);
            P[(2 * t + 1) & 7] = *(const u64*)(sxb + hr + 2 * t + 8);
        }
    }
}

// ---------------- single kernel: conv to smem, then tables-by-rotation ----------------
__global__ __launch_bounds__(NT, 3) void embed_kernel(
    const float* __restrict__ x,       // (4096, 7)
    const float* __restrict__ kern,    // (74, 8, 3)
    const int*   __restrict__ xm,      // (4096, 4)
    float*       __restrict__ out)     // (4096, 1536)
{
    extern __shared__ float smem[];
    float* __restrict__ convS = smem + SM_CONV;
    float* __restrict__ wcsS  = smem + SM_WCS;
    float* __restrict__ sxA   = smem + SM_SXA;
    float* __restrict__ sxB   = smem + SM_SXB;
    float* __restrict__ mS    = smem + SM_M;

    // balanced partition: block b owns rows [b*SEQ/NBLK, (b+1)*SEQ/NBLK)  -> 9 or 10 rows
    const int b    = blockIdx.x;
    const int s0   = (b * SEQ) / NBLK;
    const int rmax = ((b + 1) * SEQ) / NBLK - s0;
    const int tid  = threadIdx.x;

    // ---- stage weights: wc[o][k] = kern[o*24 + k*3 + 1]
    for (int e = tid; e < NUMK * KH; e += NT) {
        int o = e / KH, k = e - o * KH;
        wcsS[k * 76 + o] = kern[o * (KH * KW) + k * KW + 1];
    }
    // ---- stage x window (dual staggered copies): i in [0, WLEN), t = 3*s0 - 4 + i
    if (tid < CIN * WLEN) {
        int c = tid / WLEN, i = tid - c * WLEN;
        int t = 3 * s0 - 4 + i;
        float v = 0.0f;
        if (t >= 0 && t < TLEN) {
            int row = t / 3 + t % 3;
            if (row > SEQ - 1) row = SEQ - 1;
            v = x[row * CIN + c];
        }
        sxA[c * WPAD + i] = v;
        if (i > 0) sxB[c * WPAD + i - 1] = v;
    }
    // ---- stage temporal multiplicities (non-duplicated): mS[r][a] = #{k : xm[s][k]==a}, a==7 pad = 0
    if (tid >= 288 && tid < 288 + SPER * 8) {
        int e = tid - 288;
        int r = e >> 3, a = e & 7;
        int s = s0 + r; if (s > SEQ - 1) s = SEQ - 1;   // clamp (stores predicated off anyway)
        float m = 0.0f;
        if (a < 7) {
            const int* xr = xm + s * 4;
            m = (float)((xr[0] == a) + (xr[1] == a) + (xr[2] == a) + (xr[3] == a));
        }
        mS[r * 8 + a] = m;
    }
    __syncthreads();

    // =========== Phase 1 (balanced, fixed 30 h): full column g = tid; plus a 10-h chunk ==========
    {
        const int g = tid;                       // 0..383 -> c <= 5, never 511
        const int c = g / 73, o = g - c * 73;
        conv_col(sxA + c * WPAD, sxB + c * WPAD, wcsS, o, g, 0, NH / 2, convS);
    }
    {
        const int g  = 384 + (tid & 127);        // 384..511
        const int hr = (tid >> 7) * SPER;        // 0, 10, 20 (even)
        int c, o;
        if (g == 511) { c = 0; o = NUMK - 1; }
        else          { c = g / 73; o = g - c * 73; }
        conv_col(sxA + c * WPAD, sxB + c * WPAD, wcsS, o, g, hr, SPER / 2, convS);
    }
    __syncthreads();

    // =========== Phase 2: one float4 column per thread; pe + temporal by rotation ==========
    const int lane = tid & 127;          // 0..127
    const int jj   = tid >> 7;           // 0..2
    const int g0   = 4 * lane;
    const int f    = jj * 512 + g0;      // even; dims f..f+3 = pairs (i0, i0+1)

    const float cexp = (float)(-9.210340371976184 / 1536.0); // -ln(10000)/d
    const float div0 = expf((float)(f) * cexp);
    const float div1 = div0 * 0.988078993f;                  // * 10000^(-2/1536)

    // pe(s0) seed: large args -> accurate sincosf
    float ps0, pc0, ps1, pc1;
    sincosf((float)s0 * div0, &ps0, &pc0);
    sincosf((float)s0 * div1, &ps1, &pc1);
    // per-row rotation step: args <= 1 rad -> fast path
    float gs0, gc0, gs1, gc1;
    __sincosf(div0, &gs0, &gc0);
    __sincosf(div1, &gs1, &gc1);

    // packed temporal basis Tp[a] = (sin(a*div), cos(a*div)), a = 1..6
    u64 Tp0[7], Tp1[7];
    F2PACK(Tp0[1], gs0, gc0);
    F2PACK(Tp1[1], gs1, gc1);
    {
        float ts0 = gs0, tc0 = gc0, ts1 = gs1, tc1 = gc1;
#pragma unroll
        for (int a = 2; a <= 6; a++) {
            float ns0 = ts0 * gc0 + tc0 * gs0;
            float nc0 = tc0 * gc0 - ts0 * gs0;
            float ns1 = ts1 * gc1 + tc1 * gs1;
            float nc1 = tc1 * gc1 - ts1 * gs1;
            ts0 = ns0; tc0 = nc0; ts1 = ns1; tc1 = nc1;
            F2PACK(Tp0[a], ts0, tc0);
            F2PACK(Tp1[a], ts1, tc1);
        }
    }

    float* __restrict__ outp = out + (size_t)s0 * D + f;
    const float* __restrict__ cvp = convS + jj * 512 + g0;   // +1536 per row

#pragma unroll
    for (int r = 0; r < SPER; r++) {
        // 2x LDS.128: m0..m3, m4..m7 (m7 = pad)
        const float4 mf0 = *(const float4*)(mS + r * 8);
        const float4 mf1 = *(const float4*)(mS + r * 8 + 4);
        // conv float4 as packed pairs
        const ulonglong2 cv2 = *(const ulonglong2*)(cvp + r * 3 * 512);

        // duplicate multiplicities into packed pairs (alu pipe)
        u64 m1p, m2p, m3p, m4p, m5p, m6p;
        F2PACK(m1p, mf0.y, mf0.y);
        F2PACK(m2p, mf0.z, mf0.z);
        F2PACK(m3p, mf0.w, mf0.w);
        F2PACK(m4p, mf1.x, mf1.x);
        F2PACK(m5p, mf1.y, mf1.y);
        F2PACK(m6p, mf1.z, mf1.z);

        // seed accumulator with pe and the a=0 term (m0 on cos lane)
        u64 t0, t1;
        F2PACK(t0, ps0, pc0 + mf0.x);
        F2PACK(t1, ps1, pc1 + mf0.x);
        F2FMA(t0, m1p, Tp0[1], t0);  F2FMA(t1, m1p, Tp1[1], t1);
        F2FMA(t0, m2p, Tp0[2], t0);  F2FMA(t1, m2p, Tp1[2], t1);
        F2FMA(t0, m3p, Tp0[3], t0);  F2FMA(t1, m3p, Tp1[3], t1);
        F2FMA(t0, m4p, Tp0[4], t0);  F2FMA(t1, m4p, Tp1[4], t1);
        F2FMA(t0, m5p, Tp0[5], t0);  F2FMA(t1, m5p, Tp1[5], t1);
        F2FMA(t0, m6p, Tp0[6], t0);  F2FMA(t1, m6p, Tp1[6], t1);

        ulonglong2 res;
        F2ADD(res.x, cv2.x, t0);
        F2ADD(res.y, cv2.y, t1);
        if (r < rmax)
            *(ulonglong2*)outp = res;

        // rotate pe by div for next row
        float ns0 = ps0 * gc0 + pc0 * gs0;
        float nc0 = pc0 * gc0 - ps0 * gs0;
        float ns1 = ps1 * gc1 + pc1 * gs1;
        float nc1 = pc1 * gc1 - ps1 * gs1;
        ps0 = ns0; pc0 = nc0; ps1 = ns1; pc1 = nc1;

        outp += D;
    }
}

// ---------------- launch ----------------
extern "C" void kernel_launch(void* const* d_in, const int* in_sizes, int n_in,
                              void* d_out, int out_size)
{
    const float* x     = nullptr;
    const float* kern  = nullptr;
    const int*   xmark = nullptr;
    for (int i = 0; i < n_in; i++) {
        if      (in_sizes[i] == SEQ * CIN)        x     = (const float*)d_in[i];
        else if (in_sizes[i] == NUMK * KH * KW)   kern  = (const float*)d_in[i];
        else if (in_sizes[i] == SEQ * 4)          xmark = (const int*)d_in[i];
    }

    cudaFuncSetAttribute(embed_kernel,
                         cudaFuncAttributeMaxDynamicSharedMemorySize, SMEM_BYTES);

    embed_kernel<<<NBLK, NT, SMEM_BYTES>>>(x, kern, xmark, (float*)d_out);
}